// round 2
// baseline (speedup 1.0000x reference)
#include <cuda_runtime.h>

// Problem constants (fixed by the dataset)
#define BB 32
#define LL 1024
#define EE 256
#define HH 256
#define TT 8192
#define KD 768                 // 3*256 im2col contraction
#define MM (BB*LL)             // 32768 rows
#define OUT_OFF (BB*TT*EE)     // 67108864: duration tensor follows output tensor

// Scratch (allocation-free rule: __device__ globals)
__device__ float g_W1[KD*HH];      // transposed conv1 weights [kk][h]
__device__ float g_W2[KD*HH];
__device__ float g_H1[MM*HH];      // conv1 -> LN1 -> relu activations
__device__ float g_H2[MM*HH];      // conv2 raw output
__device__ int   g_idx[BB*TT];     // regulate gather index, -1 = zero row

// ---------------------------------------------------------------------------
// Transpose conv weights [H,E,K] -> [k*E+e][H] so GEMM B-tile loads are coalesced
// ---------------------------------------------------------------------------
__global__ void prep_weights(const float* __restrict__ c1w,
                             const float* __restrict__ c2w) {
    int i = blockIdx.x * blockDim.x + threadIdx.x;
    if (i >= KD * HH) return;
    int h  = i % HH;
    int kk = i / HH;
    int k  = kk / EE;
    int e  = kk % EE;
    g_W1[i] = c1w[(h * EE + e) * 3 + k];
    g_W2[i] = c2w[(h * EE + e) * 3 + k];
}

// ---------------------------------------------------------------------------
// conv-as-GEMM: Out[m,h] = sum_kk A[m,kk] * Wt[kk,h] + bias[h]
// A[m,kk] = X[batch_base + (l-1)*E + kk] with zero pad outside [0, L*E)
// Tiles: 128x128x16, 256 threads, 8x8 microtile per thread.
// ---------------------------------------------------------------------------
__global__ void __launch_bounds__(256, 2)
conv_gemm(const float* __restrict__ X, const float* __restrict__ Wt,
          const float* __restrict__ bias, float* __restrict__ Out) {
    __shared__ float As[16][128];
    __shared__ float Bs[16][128];

    const int tid = threadIdx.x;
    const int m0  = blockIdx.x * 128;        // row tile (aligned with batch: 1024%128==0)
    const int n0  = blockIdx.y * 128;        // col tile
    const float* xb = X + (m0 >> 10) * (LL * EE);   // batch base

    // A-load mapping: 4 threads per row (float4 over k), 2 rows per thread
    const int ar = tid >> 2;                 // 0..63
    const int ak = (tid & 3) << 2;           // 0,4,8,12
    const int l0 = (m0 + ar) & (LL - 1);
    const int l1 = (m0 + ar + 64) & (LL - 1);
    // B-load mapping: 32 threads per k-row (float4 over n), 2 k-rows per thread
    const int brr = tid >> 5;                // 0..7
    const int bc  = (tid & 31) << 2;

    const int row = (tid >> 4) << 3;         // 0..120
    const int col = (tid & 15) << 3;

    float acc[8][8];
#pragma unroll
    for (int i = 0; i < 8; i++)
#pragma unroll
        for (int j = 0; j < 8; j++) acc[i][j] = 0.f;

    for (int k0 = 0; k0 < KD; k0 += 16) {
        // ---- load A tile (with implicit im2col + zero padding) ----
        {
            const int kk = k0 + ak;
            int off0 = l0 * EE + kk - EE;
            float4 v0 = make_float4(0.f, 0.f, 0.f, 0.f);
            if (off0 >= 0 && off0 < LL * EE)
                v0 = *reinterpret_cast<const float4*>(xb + off0);
            As[ak + 0][ar] = v0.x; As[ak + 1][ar] = v0.y;
            As[ak + 2][ar] = v0.z; As[ak + 3][ar] = v0.w;

            int off1 = l1 * EE + kk - EE;
            float4 v1 = make_float4(0.f, 0.f, 0.f, 0.f);
            if (off1 >= 0 && off1 < LL * EE)
                v1 = *reinterpret_cast<const float4*>(xb + off1);
            As[ak + 0][ar + 64] = v1.x; As[ak + 1][ar + 64] = v1.y;
            As[ak + 2][ar + 64] = v1.z; As[ak + 3][ar + 64] = v1.w;
        }
        // ---- load B tile ----
        *reinterpret_cast<float4*>(&Bs[brr][bc]) =
            *reinterpret_cast<const float4*>(Wt + (k0 + brr) * HH + n0 + bc);
        *reinterpret_cast<float4*>(&Bs[brr + 8][bc]) =
            *reinterpret_cast<const float4*>(Wt + (k0 + brr + 8) * HH + n0 + bc);
        __syncthreads();

#pragma unroll
        for (int k = 0; k < 16; k++) {
            float4 a0 = *reinterpret_cast<float4*>(&As[k][row]);
            float4 a1 = *reinterpret_cast<float4*>(&As[k][row + 4]);
            float4 b0 = *reinterpret_cast<float4*>(&Bs[k][col]);
            float4 b1 = *reinterpret_cast<float4*>(&Bs[k][col + 4]);
            float a[8] = {a0.x, a0.y, a0.z, a0.w, a1.x, a1.y, a1.z, a1.w};
            float b[8] = {b0.x, b0.y, b0.z, b0.w, b1.x, b1.y, b1.z, b1.w};
#pragma unroll
            for (int i = 0; i < 8; i++)
#pragma unroll
                for (int j = 0; j < 8; j++)
                    acc[i][j] = fmaf(a[i], b[j], acc[i][j]);
        }
        __syncthreads();
    }

    // epilogue: + bias, store
    float4 bv0 = *reinterpret_cast<const float4*>(bias + n0 + col);
    float4 bv1 = *reinterpret_cast<const float4*>(bias + n0 + col + 4);
#pragma unroll
    for (int i = 0; i < 8; i++) {
        float* o = Out + (m0 + row + i) * HH + n0 + col;
        float4 s0 = make_float4(acc[i][0] + bv0.x, acc[i][1] + bv0.y,
                                acc[i][2] + bv0.z, acc[i][3] + bv0.w);
        float4 s1 = make_float4(acc[i][4] + bv1.x, acc[i][5] + bv1.y,
                                acc[i][6] + bv1.z, acc[i][7] + bv1.w);
        *reinterpret_cast<float4*>(o)     = s0;
        *reinterpret_cast<float4*>(o + 4) = s1;
    }
}

// ---------------------------------------------------------------------------
// LayerNorm(256) + ReLU, in place. One warp per row, 8 warps per block.
// ---------------------------------------------------------------------------
__global__ void ln_relu(float* __restrict__ Hm, const float* __restrict__ g,
                        const float* __restrict__ bt) {
    int warp = threadIdx.x >> 5;
    int lane = threadIdx.x & 31;
    int r = blockIdx.x * 8 + warp;
    float* p = Hm + r * HH + lane * 8;
    float4 v0 = *reinterpret_cast<float4*>(p);
    float4 v1 = *reinterpret_cast<float4*>(p + 4);
    float x[8] = {v0.x, v0.y, v0.z, v0.w, v1.x, v1.y, v1.z, v1.w};
    float s = 0.f, ss = 0.f;
#pragma unroll
    for (int i = 0; i < 8; i++) { s += x[i]; ss = fmaf(x[i], x[i], ss); }
#pragma unroll
    for (int o = 16; o; o >>= 1) {
        s  += __shfl_xor_sync(0xffffffffu, s, o);
        ss += __shfl_xor_sync(0xffffffffu, ss, o);
    }
    float mu  = s * (1.f / 256.f);
    float var = ss * (1.f / 256.f) - mu * mu;
    float inv = rsqrtf(var + 1e-5f);
    int c = lane * 8;
    float4 g0 = *reinterpret_cast<const float4*>(g + c);
    float4 g1 = *reinterpret_cast<const float4*>(g + c + 4);
    float4 b0 = *reinterpret_cast<const float4*>(bt + c);
    float4 b1 = *reinterpret_cast<const float4*>(bt + c + 4);
    float gg[8] = {g0.x, g0.y, g0.z, g0.w, g1.x, g1.y, g1.z, g1.w};
    float bb[8] = {b0.x, b0.y, b0.z, b0.w, b1.x, b1.y, b1.z, b1.w};
    float y[8];
#pragma unroll
    for (int i = 0; i < 8; i++)
        y[i] = fmaxf(fmaf((x[i] - mu) * inv, gg[i], bb[i]), 0.f);
    *reinterpret_cast<float4*>(p)     = make_float4(y[0], y[1], y[2], y[3]);
    *reinterpret_cast<float4*>(p + 4) = make_float4(y[4], y[5], y[6], y[7]);
}

// ---------------------------------------------------------------------------
// LayerNorm + ReLU + linear [H,1] + ReLU  ->  duration[b,l]
// ---------------------------------------------------------------------------
__global__ void ln_dot(const float* __restrict__ Hm, const float* __restrict__ g,
                       const float* __restrict__ bt, const float* __restrict__ lw,
                       const float* __restrict__ lb, float* __restrict__ dur) {
    int warp = threadIdx.x >> 5;
    int lane = threadIdx.x & 31;
    int r = blockIdx.x * 8 + warp;
    const float* p = Hm + r * HH + lane * 8;
    float4 v0 = *reinterpret_cast<const float4*>(p);
    float4 v1 = *reinterpret_cast<const float4*>(p + 4);
    float x[8] = {v0.x, v0.y, v0.z, v0.w, v1.x, v1.y, v1.z, v1.w};
    float s = 0.f, ss = 0.f;
#pragma unroll
    for (int i = 0; i < 8; i++) { s += x[i]; ss = fmaf(x[i], x[i], ss); }
#pragma unroll
    for (int o = 16; o; o >>= 1) {
        s  += __shfl_xor_sync(0xffffffffu, s, o);
        ss += __shfl_xor_sync(0xffffffffu, ss, o);
    }
    float mu  = s * (1.f / 256.f);
    float var = ss * (1.f / 256.f) - mu * mu;
    float inv = rsqrtf(var + 1e-5f);
    int c = lane * 8;
    float dot = 0.f;
#pragma unroll
    for (int i = 0; i < 8; i++) {
        float y = fmaxf(fmaf((x[i] - mu) * inv, g[c + i], bt[c + i]), 0.f);
        dot = fmaf(y, lw[c + i], dot);
    }
#pragma unroll
    for (int o = 16; o; o >>= 1)
        dot += __shfl_xor_sync(0xffffffffu, dot, o);
    if (lane == 0) dur[r] = fmaxf(dot + lb[0], 0.f);
}

// ---------------------------------------------------------------------------
// Per-batch cumsum of target + searchsorted(right) -> g_idx[b,t] (-1 = zero)
// ---------------------------------------------------------------------------
__global__ void scan_idx(const int* __restrict__ target) {
    __shared__ int cum[LL];
    __shared__ int ps[256];
    int b = blockIdx.x;
    int tid = threadIdx.x;
    const int* tb = target + b * LL;
    int v[4], s = 0;
#pragma unroll
    for (int i = 0; i < 4; i++) { v[i] = tb[tid * 4 + i]; s += v[i]; }
    ps[tid] = s;
    __syncthreads();
    for (int o = 1; o < 256; o <<= 1) {
        int t = (tid >= o) ? ps[tid - o] : 0;
        __syncthreads();
        ps[tid] += t;
        __syncthreads();
    }
    int run = ps[tid] - s;   // exclusive prefix of this thread's chunk
#pragma unroll
    for (int i = 0; i < 4; i++) { run += v[i]; cum[tid * 4 + i] = run; }
    __syncthreads();
    int total = cum[LL - 1];
    for (int t = tid; t < TT; t += 256) {
        int r = -1;
        if (t < total) {
            int lo = 0, hi = LL;
            while (lo < hi) {
                int mid = (lo + hi) >> 1;
                if (cum[mid] <= t) lo = mid + 1; else hi = mid;
            }
            r = lo < (LL - 1) ? lo : (LL - 1);
        }
        g_idx[b * TT + t] = r;
    }
}

// ---------------------------------------------------------------------------
// Gather/zero-fill: out[b,t,:] = (idx>=0) ? x[b,idx,:] : 0.  Write-bound.
// 256 threads = 4 rows x 64 threads (float4 per thread covers 256 floats/row)
// ---------------------------------------------------------------------------
__global__ void copy_out(const float* __restrict__ X, float* __restrict__ out) {
    int tid  = threadIdx.x;
    int rt   = blockIdx.x * 4 + (tid >> 6);
    int lane = tid & 63;
    int b = rt >> 13;          // / 8192
    int j = g_idx[rt];
    float4 val = make_float4(0.f, 0.f, 0.f, 0.f);
    if (j >= 0)
        val = *reinterpret_cast<const float4*>(X + (b * LL + j) * EE + lane * 4);
    *reinterpret_cast<float4*>(out + (size_t)rt * EE + lane * 4) = val;
}

// ---------------------------------------------------------------------------
extern "C" void kernel_launch(void* const* d_in, const int* in_sizes, int n_in,
                              void* d_out, int out_size) {
    const float* x      = (const float*)d_in[0];
    const int*   target = (const int*)  d_in[1];
    // d_in[2] = mel_max_len (constant 8192, baked in)
    const float* c1w = (const float*)d_in[3];
    const float* c1b = (const float*)d_in[4];
    const float* g1  = (const float*)d_in[5];
    const float* b1  = (const float*)d_in[6];
    const float* c2w = (const float*)d_in[7];
    const float* c2b = (const float*)d_in[8];
    const float* g2  = (const float*)d_in[9];
    const float* b2  = (const float*)d_in[10];
    const float* lw  = (const float*)d_in[11];
    const float* lb  = (const float*)d_in[12];

    float* out = (float*)d_out;
    float* dur = out + OUT_OFF;

    float *W1, *W2, *H1, *H2;
    cudaGetSymbolAddress((void**)&W1, g_W1);
    cudaGetSymbolAddress((void**)&W2, g_W2);
    cudaGetSymbolAddress((void**)&H1, g_H1);
    cudaGetSymbolAddress((void**)&H2, g_H2);

    // 1. weight transpose
    prep_weights<<<(KD * HH + 255) / 256, 256>>>(c1w, c2w);

    // 2. conv1 (GEMM) + bias
    dim3 ggrid(MM / 128, HH / 128);
    conv_gemm<<<ggrid, 256>>>(x, W1, c1b, H1);

    // 3. LN1 + relu (in place)
    ln_relu<<<MM / 8, 256>>>(H1, g1, b1);

    // 4. conv2 (GEMM) + bias
    conv_gemm<<<ggrid, 256>>>(H1, W2, c2b, H2);

    // 5. LN2 + relu + linear + relu -> duration
    ln_dot<<<MM / 8, 256>>>(H2, g2, b2, lw, lb, dur);

    // 6. length-regulate index build
    scan_idx<<<BB, 256>>>(target);

    // 7. gather/zero-fill main output
    copy_out<<<(BB * TT) / 4, 256>>>(x, out);
}

// round 3
// speedup vs baseline: 1.0025x; 1.0025x over previous
#include <cuda_runtime.h>

// Problem constants (fixed by the dataset)
#define BB 32
#define LL 1024
#define EE 256
#define HH 256
#define TT 8192
#define KD 768                 // 3*256 im2col contraction
#define MM (BB*LL)             // 32768 rows
#define OUT_OFF (BB*TT*EE)     // 67108864: duration tensor follows output tensor

// Scratch (allocation-free rule: __device__ globals)
__device__ float g_W1[KD*HH];      // transposed conv1 weights [kk][h]
__device__ float g_W2[KD*HH];
__device__ float g_H1[MM*HH];      // conv1 -> LN1 -> relu activations
__device__ float g_H2[MM*HH];      // conv2 raw output
__device__ int   g_idx[BB*TT];     // regulate gather index, -1 = zero row

// ---------------------------------------------------------------------------
// Transpose conv weights [H,E,K] -> [k*E+e][H] so GEMM B-tile loads are coalesced
// ---------------------------------------------------------------------------
__global__ void prep_weights(const float* __restrict__ c1w,
                             const float* __restrict__ c2w) {
    int i = blockIdx.x * blockDim.x + threadIdx.x;
    if (i >= KD * HH) return;
    int h  = i % HH;
    int kk = i / HH;
    int k  = kk / EE;
    int e  = kk % EE;
    g_W1[i] = c1w[(h * EE + e) * 3 + k];
    g_W2[i] = c2w[(h * EE + e) * 3 + k];
}

// ---------------------------------------------------------------------------
// conv-as-GEMM: Out[m,h] = sum_kk A[m,kk] * Wt[kk,h] + bias[h]
// A[m,kk] = X[batch_base + (l-1)*E + kk] with zero pad outside [0, L*E)
// Tiles: 128x128x16, 256 threads, 8x8 microtile per thread.
// ---------------------------------------------------------------------------
__global__ void __launch_bounds__(256, 2)
conv_gemm(const float* __restrict__ X, const float* __restrict__ Wt,
          const float* __restrict__ bias, float* __restrict__ Out) {
    __shared__ float As[16][128];
    __shared__ float Bs[16][128];

    const int tid = threadIdx.x;
    const int m0  = blockIdx.x * 128;        // row tile (aligned with batch: 1024%128==0)
    const int n0  = blockIdx.y * 128;        // col tile
    const float* xb = X + (m0 >> 10) * (LL * EE);   // batch base

    // A-load mapping: 4 threads per row (float4 over k), 2 rows per thread
    const int ar = tid >> 2;                 // 0..63
    const int ak = (tid & 3) << 2;           // 0,4,8,12
    const int l0 = (m0 + ar) & (LL - 1);
    const int l1 = (m0 + ar + 64) & (LL - 1);
    // B-load mapping: 32 threads per k-row (float4 over n), 2 k-rows per thread
    const int brr = tid >> 5;                // 0..7
    const int bc  = (tid & 31) << 2;

    const int row = (tid >> 4) << 3;         // 0..120
    const int col = (tid & 15) << 3;

    float acc[8][8];
#pragma unroll
    for (int i = 0; i < 8; i++)
#pragma unroll
        for (int j = 0; j < 8; j++) acc[i][j] = 0.f;

    for (int k0 = 0; k0 < KD; k0 += 16) {
        // ---- load A tile (with implicit im2col + zero padding) ----
        {
            const int kk = k0 + ak;
            int off0 = l0 * EE + kk - EE;
            float4 v0 = make_float4(0.f, 0.f, 0.f, 0.f);
            if (off0 >= 0 && off0 < LL * EE)
                v0 = *reinterpret_cast<const float4*>(xb + off0);
            As[ak + 0][ar] = v0.x; As[ak + 1][ar] = v0.y;
            As[ak + 2][ar] = v0.z; As[ak + 3][ar] = v0.w;

            int off1 = l1 * EE + kk - EE;
            float4 v1 = make_float4(0.f, 0.f, 0.f, 0.f);
            if (off1 >= 0 && off1 < LL * EE)
                v1 = *reinterpret_cast<const float4*>(xb + off1);
            As[ak + 0][ar + 64] = v1.x; As[ak + 1][ar + 64] = v1.y;
            As[ak + 2][ar + 64] = v1.z; As[ak + 3][ar + 64] = v1.w;
        }
        // ---- load B tile ----
        *reinterpret_cast<float4*>(&Bs[brr][bc]) =
            *reinterpret_cast<const float4*>(Wt + (k0 + brr) * HH + n0 + bc);
        *reinterpret_cast<float4*>(&Bs[brr + 8][bc]) =
            *reinterpret_cast<const float4*>(Wt + (k0 + brr + 8) * HH + n0 + bc);
        __syncthreads();

#pragma unroll
        for (int k = 0; k < 16; k++) {
            float4 a0 = *reinterpret_cast<float4*>(&As[k][row]);
            float4 a1 = *reinterpret_cast<float4*>(&As[k][row + 4]);
            float4 b0 = *reinterpret_cast<float4*>(&Bs[k][col]);
            float4 b1 = *reinterpret_cast<float4*>(&Bs[k][col + 4]);
            float a[8] = {a0.x, a0.y, a0.z, a0.w, a1.x, a1.y, a1.z, a1.w};
            float b[8] = {b0.x, b0.y, b0.z, b0.w, b1.x, b1.y, b1.z, b1.w};
#pragma unroll
            for (int i = 0; i < 8; i++)
#pragma unroll
                for (int j = 0; j < 8; j++)
                    acc[i][j] = fmaf(a[i], b[j], acc[i][j]);
        }
        __syncthreads();
    }

    // epilogue: + bias, store
    float4 bv0 = *reinterpret_cast<const float4*>(bias + n0 + col);
    float4 bv1 = *reinterpret_cast<const float4*>(bias + n0 + col + 4);
#pragma unroll
    for (int i = 0; i < 8; i++) {
        float* o = Out + (m0 + row + i) * HH + n0 + col;
        float4 s0 = make_float4(acc[i][0] + bv0.x, acc[i][1] + bv0.y,
                                acc[i][2] + bv0.z, acc[i][3] + bv0.w);
        float4 s1 = make_float4(acc[i][4] + bv1.x, acc[i][5] + bv1.y,
                                acc[i][6] + bv1.z, acc[i][7] + bv1.w);
        *reinterpret_cast<float4*>(o)     = s0;
        *reinterpret_cast<float4*>(o + 4) = s1;
    }
}

// ---------------------------------------------------------------------------
// LayerNorm(256) + ReLU, in place. One warp per row, 8 warps per block.
// ---------------------------------------------------------------------------
__global__ void ln_relu(float* __restrict__ Hm, const float* __restrict__ g,
                        const float* __restrict__ bt) {
    int warp = threadIdx.x >> 5;
    int lane = threadIdx.x & 31;
    int r = blockIdx.x * 8 + warp;
    float* p = Hm + r * HH + lane * 8;
    float4 v0 = *reinterpret_cast<float4*>(p);
    float4 v1 = *reinterpret_cast<float4*>(p + 4);
    float x[8] = {v0.x, v0.y, v0.z, v0.w, v1.x, v1.y, v1.z, v1.w};
    float s = 0.f, ss = 0.f;
#pragma unroll
    for (int i = 0; i < 8; i++) { s += x[i]; ss = fmaf(x[i], x[i], ss); }
#pragma unroll
    for (int o = 16; o; o >>= 1) {
        s  += __shfl_xor_sync(0xffffffffu, s, o);
        ss += __shfl_xor_sync(0xffffffffu, ss, o);
    }
    float mu  = s * (1.f / 256.f);
    float var = ss * (1.f / 256.f) - mu * mu;
    float inv = rsqrtf(var + 1e-5f);
    int c = lane * 8;
    float4 g0 = *reinterpret_cast<const float4*>(g + c);
    float4 g1 = *reinterpret_cast<const float4*>(g + c + 4);
    float4 b0 = *reinterpret_cast<const float4*>(bt + c);
    float4 b1 = *reinterpret_cast<const float4*>(bt + c + 4);
    float gg[8] = {g0.x, g0.y, g0.z, g0.w, g1.x, g1.y, g1.z, g1.w};
    float bb[8] = {b0.x, b0.y, b0.z, b0.w, b1.x, b1.y, b1.z, b1.w};
    float y[8];
#pragma unroll
    for (int i = 0; i < 8; i++)
        y[i] = fmaxf(fmaf((x[i] - mu) * inv, gg[i], bb[i]), 0.f);
    *reinterpret_cast<float4*>(p)     = make_float4(y[0], y[1], y[2], y[3]);
    *reinterpret_cast<float4*>(p + 4) = make_float4(y[4], y[5], y[6], y[7]);
}

// ---------------------------------------------------------------------------
// LayerNorm + ReLU + linear [H,1] + ReLU  ->  duration[b,l]
// ---------------------------------------------------------------------------
__global__ void ln_dot(const float* __restrict__ Hm, const float* __restrict__ g,
                       const float* __restrict__ bt, const float* __restrict__ lw,
                       const float* __restrict__ lb, float* __restrict__ dur) {
    int warp = threadIdx.x >> 5;
    int lane = threadIdx.x & 31;
    int r = blockIdx.x * 8 + warp;
    const float* p = Hm + r * HH + lane * 8;
    float4 v0 = *reinterpret_cast<const float4*>(p);
    float4 v1 = *reinterpret_cast<const float4*>(p + 4);
    float x[8] = {v0.x, v0.y, v0.z, v0.w, v1.x, v1.y, v1.z, v1.w};
    float s = 0.f, ss = 0.f;
#pragma unroll
    for (int i = 0; i < 8; i++) { s += x[i]; ss = fmaf(x[i], x[i], ss); }
#pragma unroll
    for (int o = 16; o; o >>= 1) {
        s  += __shfl_xor_sync(0xffffffffu, s, o);
        ss += __shfl_xor_sync(0xffffffffu, ss, o);
    }
    float mu  = s * (1.f / 256.f);
    float var = ss * (1.f / 256.f) - mu * mu;
    float inv = rsqrtf(var + 1e-5f);
    int c = lane * 8;
    float dot = 0.f;
#pragma unroll
    for (int i = 0; i < 8; i++) {
        float y = fmaxf(fmaf((x[i] - mu) * inv, g[c + i], bt[c + i]), 0.f);
        dot = fmaf(y, lw[c + i], dot);
    }
#pragma unroll
    for (int o = 16; o; o >>= 1)
        dot += __shfl_xor_sync(0xffffffffu, dot, o);
    if (lane == 0) dur[r] = fmaxf(dot + lb[0], 0.f);
}

// ---------------------------------------------------------------------------
// Per-batch cumsum of target + searchsorted(right) -> g_idx[b,t] (-1 = zero)
// ---------------------------------------------------------------------------
__global__ void scan_idx(const int* __restrict__ target) {
    __shared__ int cum[LL];
    __shared__ int ps[256];
    int b = blockIdx.x;
    int tid = threadIdx.x;
    const int* tb = target + b * LL;
    int v[4], s = 0;
#pragma unroll
    for (int i = 0; i < 4; i++) { v[i] = tb[tid * 4 + i]; s += v[i]; }
    ps[tid] = s;
    __syncthreads();
    for (int o = 1; o < 256; o <<= 1) {
        int t = (tid >= o) ? ps[tid - o] : 0;
        __syncthreads();
        ps[tid] += t;
        __syncthreads();
    }
    int run = ps[tid] - s;   // exclusive prefix of this thread's chunk
#pragma unroll
    for (int i = 0; i < 4; i++) { run += v[i]; cum[tid * 4 + i] = run; }
    __syncthreads();
    int total = cum[LL - 1];
    for (int t = tid; t < TT; t += 256) {
        int r = -1;
        if (t < total) {
            int lo = 0, hi = LL;
            while (lo < hi) {
                int mid = (lo + hi) >> 1;
                if (cum[mid] <= t) lo = mid + 1; else hi = mid;
            }
            r = lo < (LL - 1) ? lo : (LL - 1);
        }
        g_idx[b * TT + t] = r;
    }
}

// ---------------------------------------------------------------------------
// Gather/zero-fill: out[b,t,:] = (idx>=0) ? x[b,idx,:] : 0.  Write-bound.
// 256 threads = 4 rows x 64 threads (float4 per thread covers 256 floats/row)
// ---------------------------------------------------------------------------
__global__ void copy_out(const float* __restrict__ X, float* __restrict__ out) {
    int tid  = threadIdx.x;
    int rt   = blockIdx.x * 4 + (tid >> 6);
    int lane = tid & 63;
    int b = rt >> 13;          // / 8192
    int j = g_idx[rt];
    float4 val = make_float4(0.f, 0.f, 0.f, 0.f);
    if (j >= 0)
        val = *reinterpret_cast<const float4*>(X + (b * LL + j) * EE + lane * 4);
    *reinterpret_cast<float4*>(out + (size_t)rt * EE + lane * 4) = val;
}

// ---------------------------------------------------------------------------
extern "C" void kernel_launch(void* const* d_in, const int* in_sizes, int n_in,
                              void* d_out, int out_size) {
    const float* x      = (const float*)d_in[0];
    const int*   target = (const int*)  d_in[1];
    // d_in[2] = mel_max_len (constant 8192, baked in)
    const float* c1w = (const float*)d_in[3];
    const float* c1b = (const float*)d_in[4];
    const float* g1  = (const float*)d_in[5];
    const float* b1  = (const float*)d_in[6];
    const float* c2w = (const float*)d_in[7];
    const float* c2b = (const float*)d_in[8];
    const float* g2  = (const float*)d_in[9];
    const float* b2  = (const float*)d_in[10];
    const float* lw  = (const float*)d_in[11];
    const float* lb  = (const float*)d_in[12];

    float* out = (float*)d_out;
    float* dur = out + OUT_OFF;

    float *W1, *W2, *H1, *H2;
    cudaGetSymbolAddress((void**)&W1, g_W1);
    cudaGetSymbolAddress((void**)&W2, g_W2);
    cudaGetSymbolAddress((void**)&H1, g_H1);
    cudaGetSymbolAddress((void**)&H2, g_H2);

    // 1. weight transpose
    prep_weights<<<(KD * HH + 255) / 256, 256>>>(c1w, c2w);

    // 2. conv1 (GEMM) + bias
    dim3 ggrid(MM / 128, HH / 128);
    conv_gemm<<<ggrid, 256>>>(x, W1, c1b, H1);

    // 3. LN1 + relu (in place)
    ln_relu<<<MM / 8, 256>>>(H1, g1, b1);

    // 4. conv2 (GEMM) + bias
    conv_gemm<<<ggrid, 256>>>(H1, W2, c2b, H2);

    // 5. LN2 + relu + linear + relu -> duration
    ln_dot<<<MM / 8, 256>>>(H2, g2, b2, lw, lb, dur);

    // 6. length-regulate index build
    scan_idx<<<BB, 256>>>(target);

    // 7. gather/zero-fill main output
    copy_out<<<(BB * TT) / 4, 256>>>(x, out);
}